// round 1
// baseline (speedup 1.0000x reference)
#include <cuda_runtime.h>
#include <math.h>

#define NB 32
#define NC 256
#define NH 64
#define NW 64
#define NHW 4096
#define NCHW (NC*NHW)
#define EPSV 1e-5f

// Scratch (allocation-free rule: __device__ globals)
__device__ float g_pooled[NB*NC];
__device__ int   g_idx[NB];
__device__ float g_feat[(size_t)NB*NCHW];   // 134 MB fp32 feature scratch

// ---------------------------------------------------------------------------
// 1) Global average pool per (b,c): one block per channel-image
// ---------------------------------------------------------------------------
__global__ void pool_kernel(const float* __restrict__ x) {
    int bc = blockIdx.x;
    const float4* p = reinterpret_cast<const float4*>(x + (size_t)bc * NHW);
    float s = 0.f;
    for (int i = threadIdx.x; i < NHW/4; i += 256) {
        float4 v = p[i];
        s += (v.x + v.y) + (v.z + v.w);
    }
    __shared__ float red[8];
    #pragma unroll
    for (int o = 16; o > 0; o >>= 1) s += __shfl_down_sync(0xffffffffu, s, o);
    if ((threadIdx.x & 31) == 0) red[threadIdx.x >> 5] = s;
    __syncthreads();
    if (threadIdx.x < 8) {
        float t = red[threadIdx.x];
        #pragma unroll
        for (int o = 4; o > 0; o >>= 1) t += __shfl_down_sync(0xffu, t, o);
        if (threadIdx.x == 0) g_pooled[bc] = t * (1.0f / NHW);
    }
}

// ---------------------------------------------------------------------------
// 2) Router: logits = pooled @ rw.T + rb ; idx = argmax (softmax is monotone,
//    top-1 weight is exactly 1.0)
// ---------------------------------------------------------------------------
__global__ void route_kernel(const float* __restrict__ rw, const float* __restrict__ rb) {
    int b = threadIdx.x;
    if (b >= NB) return;
    float best = -1e30f; int bi = 0;
    #pragma unroll
    for (int j = 0; j < 3; j++) {
        float s = rb[j];
        const float* w = rw + j*NC;
        const float* p = g_pooled + b*NC;
        for (int c = 0; c < NC; c++) s = fmaf(p[c], w[c], s);
        if (s > best) { best = s; bi = j; }   // strict > : first-max wins (jax top_k tie rule)
    }
    g_idx[b] = bi;
}

// ---------------------------------------------------------------------------
// 3a) Depthwise 3x3 conv (dil 1 or 2) + BN + exact GELU for experts 0/1
//     block = (64,4): one 4-row x 64-col slab of one (b,c) plane
// ---------------------------------------------------------------------------
__global__ void dwconv_bn_gelu_kernel(
    const float* __restrict__ x,
    const float* __restrict__ k0, const float* __restrict__ g0, const float* __restrict__ b0,
    const float* __restrict__ m0, const float* __restrict__ v0,
    const float* __restrict__ k1, const float* __restrict__ g1, const float* __restrict__ b1,
    const float* __restrict__ m1, const float* __restrict__ v1)
{
    int b = blockIdx.z;
    int e = g_idx[b];
    if (e == 2) return;
    int c  = blockIdx.y;
    int y  = blockIdx.x * 4 + threadIdx.y;
    int xx = threadIdx.x;
    const float* kw = (e == 0 ? k0 : k1) + c * 9;
    int dil = e + 1;
    const float* xp = x + ((size_t)b*NC + c) * NHW;

    float acc = 0.f;
    #pragma unroll
    for (int dy = -1; dy <= 1; dy++) {
        int yy = y + dy*dil;
        if (yy < 0 || yy >= NH) continue;
        #pragma unroll
        for (int dx = -1; dx <= 1; dx++) {
            int xc = xx + dx*dil;
            if (xc < 0 || xc >= NW) continue;
            acc = fmaf(kw[(dy+1)*3 + (dx+1)], xp[yy*NW + xc], acc);
        }
    }
    float gg = (e == 0 ? g0[c] : g1[c]);
    float vv = (e == 0 ? v0[c] : v1[c]);
    float mm = (e == 0 ? m0[c] : m1[c]);
    float bb = (e == 0 ? b0[c] : b1[c]);
    float scale = gg * rsqrtf(vv + EPSV);
    float z = (acc - mm) * scale + bb;
    float r = z * normcdff(z);               // exact GELU: x * Phi(x)
    g_feat[((size_t)b*NC + c) * NHW + y*NW + xx] = r;
}

// ---------------------------------------------------------------------------
// Shared SGEMM tile: C(128x128) = A(128xK) * B(Kx128), K=256, all dims divide.
// A row-major ld=256, B row-major ld=4096, C row-major ld=4096.
// 256 threads, 8x8 per thread, BK=8.
// ---------------------------------------------------------------------------
template<bool BN_GELU>
__device__ __forceinline__ void sgemm_tile(
    const float* __restrict__ A, const float* __restrict__ Bm, float* __restrict__ Cm,
    const float* __restrict__ p0, const float* __restrict__ p1,
    const float* __restrict__ p2, const float* __restrict__ p3)
{
    __shared__ float As[8][128];
    __shared__ float Bs[8][128];
    const int tid = threadIdx.x;
    const int m0 = blockIdx.y * 128;
    const int n0 = blockIdx.x * 128;
    const int tx = tid & 15, ty = tid >> 4;
    const int arow = tid >> 1, aseg = (tid & 1) * 4;
    const int brow = tid >> 5, bcol = (tid & 31) * 4;

    float acc[8][8];
    #pragma unroll
    for (int i = 0; i < 8; i++)
        #pragma unroll
        for (int j = 0; j < 8; j++) acc[i][j] = 0.f;

    for (int k0 = 0; k0 < NC; k0 += 8) {
        float4 av = *reinterpret_cast<const float4*>(A + (size_t)(m0+arow)*NC + k0 + aseg);
        float4 bv = *reinterpret_cast<const float4*>(Bm + (size_t)(k0+brow)*NHW + n0 + bcol);
        __syncthreads();          // previous compute done before smem overwrite
        As[aseg+0][arow] = av.x;
        As[aseg+1][arow] = av.y;
        As[aseg+2][arow] = av.z;
        As[aseg+3][arow] = av.w;
        *reinterpret_cast<float4*>(&Bs[brow][bcol]) = bv;
        __syncthreads();

        #pragma unroll
        for (int kk = 0; kk < 8; kk++) {
            float ra[8], rb_[8];
            #pragma unroll
            for (int i = 0; i < 8; i++) ra[i]  = As[kk][ty*8 + i];
            #pragma unroll
            for (int j = 0; j < 8; j++) rb_[j] = Bs[kk][tx*8 + j];
            #pragma unroll
            for (int i = 0; i < 8; i++)
                #pragma unroll
                for (int j = 0; j < 8; j++)
                    acc[i][j] = fmaf(ra[i], rb_[j], acc[i][j]);
        }
    }

    #pragma unroll
    for (int i = 0; i < 8; i++) {
        int o = m0 + ty*8 + i;
        float sc = 0.f, mm = 0.f, bb;
        if (BN_GELU) {
            sc = p0[o] * rsqrtf(p3[o] + EPSV);
            mm = p2[o];
            bb = p1[o];
        } else {
            bb = p0[o];
        }
        float vals[8];
        #pragma unroll
        for (int j = 0; j < 8; j++) {
            float z = acc[i][j];
            if (BN_GELU) {
                z = (z - mm) * sc + bb;
                z = z * normcdff(z);
            } else {
                z += bb;
            }
            vals[j] = z;
        }
        float* cp = Cm + (size_t)o * NHW + n0 + tx*8;
        *reinterpret_cast<float4*>(cp)     = make_float4(vals[0], vals[1], vals[2], vals[3]);
        *reinterpret_cast<float4*>(cp + 4) = make_float4(vals[4], vals[5], vals[6], vals[7]);
    }
}

// 3b) Expert-2 feature stage: feat = bn_gelu(e2_k @ x[b]) — only for idx==2
__global__ void __launch_bounds__(256) feat_gemm_kernel(
    const float* __restrict__ x, const float* __restrict__ e2k,
    const float* __restrict__ g, const float* __restrict__ bt,
    const float* __restrict__ m, const float* __restrict__ v)
{
    int b = blockIdx.z;
    if (g_idx[b] != 2) return;
    sgemm_tile<true>(e2k, x + (size_t)b*NCHW, g_feat + (size_t)b*NCHW, g, bt, m, v);
}

// 4) Final pointwise: out[b] = e{idx}_pw @ feat[b] + e{idx}_pb
__global__ void __launch_bounds__(256) out_gemm_kernel(
    const float* __restrict__ w0, const float* __restrict__ pb0,
    const float* __restrict__ w1, const float* __restrict__ pb1,
    const float* __restrict__ w2, const float* __restrict__ pb2,
    float* __restrict__ out)
{
    int b = blockIdx.z;
    int e = g_idx[b];
    const float* A  = (e == 0) ? w0  : (e == 1 ? w1  : w2);
    const float* pb = (e == 0) ? pb0 : (e == 1 ? pb1 : pb2);
    sgemm_tile<false>(A, g_feat + (size_t)b*NCHW, out + (size_t)b*NCHW,
                      pb, nullptr, nullptr, nullptr);
}

// ---------------------------------------------------------------------------
extern "C" void kernel_launch(void* const* d_in, const int* in_sizes, int n_in,
                              void* d_out, int out_size) {
    const float* x    = (const float*)d_in[0];
    const float* rw   = (const float*)d_in[1];
    const float* rb   = (const float*)d_in[2];
    const float* e0_k = (const float*)d_in[3];
    const float* e0_g = (const float*)d_in[4];
    const float* e0_b = (const float*)d_in[5];
    const float* e0_m = (const float*)d_in[6];
    const float* e0_v = (const float*)d_in[7];
    const float* e0_pw= (const float*)d_in[8];
    const float* e0_pb= (const float*)d_in[9];
    const float* e1_k = (const float*)d_in[10];
    const float* e1_g = (const float*)d_in[11];
    const float* e1_b = (const float*)d_in[12];
    const float* e1_m = (const float*)d_in[13];
    const float* e1_v = (const float*)d_in[14];
    const float* e1_pw= (const float*)d_in[15];
    const float* e1_pb= (const float*)d_in[16];
    const float* e2_k = (const float*)d_in[17];
    const float* e2_g = (const float*)d_in[18];
    const float* e2_b = (const float*)d_in[19];
    const float* e2_m = (const float*)d_in[20];
    const float* e2_v = (const float*)d_in[21];
    const float* e2_pw= (const float*)d_in[22];
    const float* e2_pb= (const float*)d_in[23];
    float* out = (float*)d_out;

    pool_kernel<<<NB*NC, 256>>>(x);
    route_kernel<<<1, 32>>>(rw, rb);

    dim3 cgrid(NH/4, NC, NB);
    dwconv_bn_gelu_kernel<<<cgrid, dim3(64, 4, 1)>>>(
        x, e0_k, e0_g, e0_b, e0_m, e0_v,
           e1_k, e1_g, e1_b, e1_m, e1_v);

    dim3 ggrid(NHW/128, NC/128, NB);   // (32, 2, 32)
    feat_gemm_kernel<<<ggrid, 256>>>(x, e2_k, e2_g, e2_b, e2_m, e2_v);
    out_gemm_kernel<<<ggrid, 256>>>(e0_pw, e0_pb, e1_pw, e1_pb, e2_pw, e2_pb, out);
}

// round 2
// speedup vs baseline: 1.7618x; 1.7618x over previous
#include <cuda_runtime.h>
#include <math.h>
#include <stdint.h>

#define NB 32
#define NC 256
#define NH 64
#define NW 64
#define NHW 4096
#define NCHW (NC*NHW)
#define EPSV 1e-5f

// Scratch (allocation-free rule: __device__ globals)
__device__ float g_pooled[NB*NC];
__device__ int   g_idx[NB];
__device__ float g_feat[(size_t)NB*NCHW];   // 134 MB fp32 feature scratch

// ---------------------------------------------------------------------------
// 1) Global average pool per (b,c)
// ---------------------------------------------------------------------------
__global__ void pool_kernel(const float* __restrict__ x) {
    int bc = blockIdx.x;
    const float4* p = reinterpret_cast<const float4*>(x + (size_t)bc * NHW);
    float s = 0.f;
    for (int i = threadIdx.x; i < NHW/4; i += 256) {
        float4 v = p[i];
        s += (v.x + v.y) + (v.z + v.w);
    }
    __shared__ float red[8];
    #pragma unroll
    for (int o = 16; o > 0; o >>= 1) s += __shfl_down_sync(0xffffffffu, s, o);
    if ((threadIdx.x & 31) == 0) red[threadIdx.x >> 5] = s;
    __syncthreads();
    if (threadIdx.x < 8) {
        float t = red[threadIdx.x];
        #pragma unroll
        for (int o = 4; o > 0; o >>= 1) t += __shfl_down_sync(0xffu, t, o);
        if (threadIdx.x == 0) g_pooled[bc] = t * (1.0f / NHW);
    }
}

// ---------------------------------------------------------------------------
// 2) Router: argmax of logits (softmax monotone; top-1 weight == 1 exactly)
// ---------------------------------------------------------------------------
__global__ void route_kernel(const float* __restrict__ rw, const float* __restrict__ rb) {
    int b = threadIdx.x;
    if (b >= NB) return;
    float best = -1e30f; int bi = 0;
    #pragma unroll
    for (int j = 0; j < 3; j++) {
        float s = rb[j];
        const float* w = rw + j*NC;
        const float* p = g_pooled + b*NC;
        for (int c = 0; c < NC; c++) s = fmaf(p[c], w[c], s);
        if (s > best) { best = s; bi = j; }
    }
    g_idx[b] = bi;
}

// ---------------------------------------------------------------------------
// 3a) Depthwise 3x3 conv (dil 1 or 2) + BN + exact GELU for experts 0/1
// ---------------------------------------------------------------------------
__global__ void dwconv_bn_gelu_kernel(
    const float* __restrict__ x,
    const float* __restrict__ k0, const float* __restrict__ g0, const float* __restrict__ b0,
    const float* __restrict__ m0, const float* __restrict__ v0,
    const float* __restrict__ k1, const float* __restrict__ g1, const float* __restrict__ b1,
    const float* __restrict__ m1, const float* __restrict__ v1)
{
    int b = blockIdx.z;
    int e = g_idx[b];
    if (e == 2) return;
    int c  = blockIdx.y;
    int y  = blockIdx.x * 4 + threadIdx.y;
    int xx = threadIdx.x;
    const float* kw = (e == 0 ? k0 : k1) + c * 9;
    int dil = e + 1;
    const float* xp = x + ((size_t)b*NC + c) * NHW;

    float acc = 0.f;
    #pragma unroll
    for (int dy = -1; dy <= 1; dy++) {
        int yy = y + dy*dil;
        if (yy < 0 || yy >= NH) continue;
        #pragma unroll
        for (int dx = -1; dx <= 1; dx++) {
            int xc = xx + dx*dil;
            if (xc < 0 || xc >= NW) continue;
            acc = fmaf(kw[(dy+1)*3 + (dx+1)], xp[yy*NW + xc], acc);
        }
    }
    float gg = (e == 0 ? g0[c] : g1[c]);
    float vv = (e == 0 ? v0[c] : v1[c]);
    float mm = (e == 0 ? m0[c] : m1[c]);
    float bb = (e == 0 ? b0[c] : b1[c]);
    float scale = gg * rsqrtf(vv + EPSV);
    float z = (acc - mm) * scale + bb;
    float r = z * normcdff(z);               // exact GELU
    g_feat[((size_t)b*NC + c) * NHW + y*NW + xx] = r;
}

// ---------------------------------------------------------------------------
// TF32 tensor-core GEMM tile: C(128x128) = A(128x256) * B(256x128)
// A row-major ld=256, B row-major ld=4096, C row-major ld=4096.
// 256 threads, 8 warps; warp tile 32x64 via m16n8k8 tf32 mma.
// ---------------------------------------------------------------------------
__device__ __forceinline__ uint32_t f2tf32(float f) {
    uint32_t r;
    asm("cvt.rna.tf32.f32 %0, %1;" : "=r"(r) : "f"(f));
    return r;
}

__device__ __forceinline__ void mma_tf32(float c[4], const uint32_t a[4], const uint32_t b[2]) {
    asm volatile(
        "mma.sync.aligned.m16n8k8.row.col.f32.tf32.tf32.f32 "
        "{%0,%1,%2,%3}, {%4,%5,%6,%7}, {%8,%9}, {%0,%1,%2,%3};"
        : "+f"(c[0]), "+f"(c[1]), "+f"(c[2]), "+f"(c[3])
        : "r"(a[0]), "r"(a[1]), "r"(a[2]), "r"(a[3]),
          "r"(b[0]), "r"(b[1]));
}

#define SPAD 136   // row stride: 136 % 32 == 8 -> frag loads (8*qid + gID) conflict-free

template<bool BN_GELU>
__device__ __forceinline__ void mma_gemm_tile(
    const float* __restrict__ A, const float* __restrict__ Bm, float* __restrict__ Cm,
    const float* __restrict__ p0, const float* __restrict__ p1,
    const float* __restrict__ p2, const float* __restrict__ p3)
{
    __shared__ uint32_t As[2][16][SPAD];
    __shared__ uint32_t Bs[2][16][SPAD];

    const int tid  = threadIdx.x;
    const int lane = tid & 31;
    const int wid  = tid >> 5;
    const int wm   = wid & 3;        // 0..3 -> 32-row slab
    const int wn   = wid >> 2;       // 0..1 -> 64-col slab
    const int gID  = lane >> 2;      // 0..7
    const int qid  = lane & 3;       // 0..3
    const int m0   = blockIdx.y * 128;
    const int n0   = blockIdx.x * 128;

    // A tile load mapping: 128 rows x 4 float4 (16 k). 512 float4 / 256 thr = 2.
    const int am  = tid >> 2;        // row 0..63 (second load: +64)
    const int aq  = tid & 3;         // k-group-of-4
    // B tile load mapping: 16 rows(k) x 32 float4 (128 n). idx = tid, tid+256.
    const int bk  = tid >> 5;        // 0..7 (second: +8)
    const int bn4 = (tid & 31) * 4;  // n offset

    float acc[2][8][4];
    #pragma unroll
    for (int i = 0; i < 2; i++)
        #pragma unroll
        for (int j = 0; j < 8; j++)
            #pragma unroll
            for (int t = 0; t < 4; t++) acc[i][j][t] = 0.f;

    // ---- preload k0 = 0 into buffer 0 ----
    {
        float4 a0 = *reinterpret_cast<const float4*>(A + (size_t)(m0 + am)      * NC + aq*4);
        float4 a1 = *reinterpret_cast<const float4*>(A + (size_t)(m0 + am + 64) * NC + aq*4);
        float4 b0 = *reinterpret_cast<const float4*>(Bm + (size_t)(bk)     * NHW + n0 + bn4);
        float4 b1 = *reinterpret_cast<const float4*>(Bm + (size_t)(bk + 8) * NHW + n0 + bn4);
        #pragma unroll
        for (int j = 0; j < 4; j++) {
            As[0][aq*4 + j][am]      = f2tf32((&a0.x)[j]);
            As[0][aq*4 + j][am + 64] = f2tf32((&a1.x)[j]);
        }
        uint32_t* bp0 = &Bs[0][bk][bn4];
        uint32_t* bp1 = &Bs[0][bk + 8][bn4];
        bp0[0]=f2tf32(b0.x); bp0[1]=f2tf32(b0.y); bp0[2]=f2tf32(b0.z); bp0[3]=f2tf32(b0.w);
        bp1[0]=f2tf32(b1.x); bp1[1]=f2tf32(b1.y); bp1[2]=f2tf32(b1.z); bp1[3]=f2tf32(b1.w);
    }
    __syncthreads();

    int buf = 0;
    for (int k0 = 0; k0 < NC; k0 += 16) {
        const bool has_next = (k0 + 16) < NC;
        float4 a0n, a1n, b0n, b1n;
        if (has_next) {
            int kn = k0 + 16;
            a0n = *reinterpret_cast<const float4*>(A + (size_t)(m0 + am)      * NC + kn + aq*4);
            a1n = *reinterpret_cast<const float4*>(A + (size_t)(m0 + am + 64) * NC + kn + aq*4);
            b0n = *reinterpret_cast<const float4*>(Bm + (size_t)(kn + bk)     * NHW + n0 + bn4);
            b1n = *reinterpret_cast<const float4*>(Bm + (size_t)(kn + bk + 8) * NHW + n0 + bn4);
        }

        // ---- compute on smem[buf] ----
        #pragma unroll
        for (int ks = 0; ks < 2; ks++) {
            const int kb = ks * 8;
            uint32_t af[2][4], bf[8][2];
            #pragma unroll
            for (int mt = 0; mt < 2; mt++) {
                const int mb = wm*32 + mt*16;
                af[mt][0] = As[buf][kb + qid]    [mb + gID];
                af[mt][1] = As[buf][kb + qid]    [mb + gID + 8];
                af[mt][2] = As[buf][kb + 4 + qid][mb + gID];
                af[mt][3] = As[buf][kb + 4 + qid][mb + gID + 8];
            }
            #pragma unroll
            for (int nt = 0; nt < 8; nt++) {
                const int nb = wn*64 + nt*8;
                bf[nt][0] = Bs[buf][kb + qid]    [nb + gID];
                bf[nt][1] = Bs[buf][kb + 4 + qid][nb + gID];
            }
            #pragma unroll
            for (int mt = 0; mt < 2; mt++)
                #pragma unroll
                for (int nt = 0; nt < 8; nt++)
                    mma_tf32(acc[mt][nt], af[mt], bf[nt]);
        }

        if (has_next) {
            const int nb_ = buf ^ 1;
            #pragma unroll
            for (int j = 0; j < 4; j++) {
                As[nb_][aq*4 + j][am]      = f2tf32((&a0n.x)[j]);
                As[nb_][aq*4 + j][am + 64] = f2tf32((&a1n.x)[j]);
            }
            uint32_t* bp0 = &Bs[nb_][bk][bn4];
            uint32_t* bp1 = &Bs[nb_][bk + 8][bn4];
            bp0[0]=f2tf32(b0n.x); bp0[1]=f2tf32(b0n.y); bp0[2]=f2tf32(b0n.z); bp0[3]=f2tf32(b0n.w);
            bp1[0]=f2tf32(b1n.x); bp1[1]=f2tf32(b1n.y); bp1[2]=f2tf32(b1n.z); bp1[3]=f2tf32(b1n.w);
            __syncthreads();
            buf = nb_;
        }
    }

    // ---- epilogue ----
    #pragma unroll
    for (int mt = 0; mt < 2; mt++) {
        #pragma unroll
        for (int half = 0; half < 2; half++) {
            const int o = m0 + wm*32 + mt*16 + half*8 + gID;
            float sc = 0.f, mm = 0.f, bb;
            if (BN_GELU) {
                sc = p0[o] * rsqrtf(p3[o] + EPSV);
                mm = p2[o];
                bb = p1[o];
            } else {
                bb = p0[o];
            }
            float* cp = Cm + (size_t)o * NHW + n0 + wn*64 + qid*2;
            #pragma unroll
            for (int nt = 0; nt < 8; nt++) {
                float z0 = acc[mt][nt][half*2 + 0];
                float z1 = acc[mt][nt][half*2 + 1];
                if (BN_GELU) {
                    z0 = (z0 - mm) * sc + bb; z0 = z0 * normcdff(z0);
                    z1 = (z1 - mm) * sc + bb; z1 = z1 * normcdff(z1);
                } else {
                    z0 += bb; z1 += bb;
                }
                *reinterpret_cast<float2*>(cp + nt*8) = make_float2(z0, z1);
            }
        }
    }
}

// 3b) Expert-2 feature stage: feat = bn_gelu(e2_k @ x[b]) — only for idx==2
__global__ void __launch_bounds__(256, 2) feat_gemm_kernel(
    const float* __restrict__ x, const float* __restrict__ e2k,
    const float* __restrict__ g, const float* __restrict__ bt,
    const float* __restrict__ m, const float* __restrict__ v)
{
    int b = blockIdx.z;
    if (g_idx[b] != 2) return;
    mma_gemm_tile<true>(e2k, x + (size_t)b*NCHW, g_feat + (size_t)b*NCHW, g, bt, m, v);
}

// 4) Final pointwise: out[b] = e{idx}_pw @ feat[b] + e{idx}_pb
__global__ void __launch_bounds__(256, 2) out_gemm_kernel(
    const float* __restrict__ w0, const float* __restrict__ pb0,
    const float* __restrict__ w1, const float* __restrict__ pb1,
    const float* __restrict__ w2, const float* __restrict__ pb2,
    float* __restrict__ out)
{
    int b = blockIdx.z;
    int e = g_idx[b];
    const float* A  = (e == 0) ? w0  : (e == 1 ? w1  : w2);
    const float* pb = (e == 0) ? pb0 : (e == 1 ? pb1 : pb2);
    mma_gemm_tile<false>(A, g_feat + (size_t)b*NCHW, out + (size_t)b*NCHW,
                         pb, nullptr, nullptr, nullptr);
}

// ---------------------------------------------------------------------------
extern "C" void kernel_launch(void* const* d_in, const int* in_sizes, int n_in,
                              void* d_out, int out_size) {
    const float* x    = (const float*)d_in[0];
    const float* rw   = (const float*)d_in[1];
    const float* rb   = (const float*)d_in[2];
    const float* e0_k = (const float*)d_in[3];
    const float* e0_g = (const float*)d_in[4];
    const float* e0_b = (const float*)d_in[5];
    const float* e0_m = (const float*)d_in[6];
    const float* e0_v = (const float*)d_in[7];
    const float* e0_pw= (const float*)d_in[8];
    const float* e0_pb= (const float*)d_in[9];
    const float* e1_k = (const float*)d_in[10];
    const float* e1_g = (const float*)d_in[11];
    const float* e1_b = (const float*)d_in[12];
    const float* e1_m = (const float*)d_in[13];
    const float* e1_v = (const float*)d_in[14];
    const float* e1_pw= (const float*)d_in[15];
    const float* e1_pb= (const float*)d_in[16];
    const float* e2_k = (const float*)d_in[17];
    const float* e2_g = (const float*)d_in[18];
    const float* e2_b = (const float*)d_in[19];
    const float* e2_m = (const float*)d_in[20];
    const float* e2_v = (const float*)d_in[21];
    const float* e2_pw= (const float*)d_in[22];
    const float* e2_pb= (const float*)d_in[23];
    float* out = (float*)d_out;

    pool_kernel<<<NB*NC, 256>>>(x);
    route_kernel<<<1, 32>>>(rw, rb);

    dim3 cgrid(NH/4, NC, NB);
    dwconv_bn_gelu_kernel<<<cgrid, dim3(64, 4, 1)>>>(
        x, e0_k, e0_g, e0_b, e0_m, e0_v,
           e1_k, e1_g, e1_b, e1_m, e1_v);

    dim3 ggrid(NHW/128, NC/128, NB);   // (32, 2, 32)
    feat_gemm_kernel<<<ggrid, 256>>>(x, e2_k, e2_g, e2_b, e2_m, e2_v);
    out_gemm_kernel<<<ggrid, 256>>>(e0_pw, e0_pb, e1_pw, e1_pb, e2_pw, e2_pb, out);
}